// round 2
// baseline (speedup 1.0000x reference)
#include <cuda_runtime.h>
#include <math.h>

#define N_NODES 100000
#define N_EDGES 1600000
#define HID 128

// ---------------- scratch (static __device__, no allocation) ----------------
__device__ float g_feat0[N_NODES * 3];          // h after conv1 (C=3)
__device__ float g_featA[N_NODES * HID];        // node features buffer A
__device__ float g_featB[N_NODES * HID];        // node features buffer B
__device__ float g_tab[N_NODES * 512];          // per-node pre-projection table
__device__ float g_Wcat[128 * 512];             // packed [Wf_dst|Ws_dst|Wf_src|Ws_src]
__device__ float g_bcat[512];                   // packed bias [bf|bs|0|0]
__device__ float g_pool[64 * HID];
__device__ float g_cnt[64];

// ---------------- math helpers ----------------
__device__ __forceinline__ float sigmoidf_(float x) {
    return 1.0f / (1.0f + __expf(-x));
}
__device__ __forceinline__ float softplusf_(float x) {
    // stable: large x -> x ; otherwise log1p(exp(x))
    return (x > 20.0f) ? x : log1pf(__expf(x));
}

// ---------------- conv1: CGConv at C=3 (thread per edge) ----------------
__global__ void conv1_kernel(const float* __restrict__ x,
                             const int* __restrict__ src,
                             const int* __restrict__ dst,
                             const float* __restrict__ ea,
                             const float* __restrict__ Wf,
                             const float* __restrict__ bf,
                             const float* __restrict__ Ws,
                             const float* __restrict__ bs,
                             float* __restrict__ out) {
    __shared__ float sWf[38 * 3];
    __shared__ float sWs[38 * 3];
    __shared__ float sbf[3], sbs[3];
    for (int i = threadIdx.x; i < 38 * 3; i += blockDim.x) {
        sWf[i] = Wf[i];
        sWs[i] = Ws[i];
    }
    if (threadIdx.x < 3) { sbf[threadIdx.x] = bf[threadIdx.x]; sbs[threadIdx.x] = bs[threadIdx.x]; }
    __syncthreads();

    int e = blockIdx.x * blockDim.x + threadIdx.x;
    if (e >= N_EDGES) return;
    int s = src[e], d = dst[e];

    float z[38];
    z[0] = x[d * 3 + 0]; z[1] = x[d * 3 + 1]; z[2] = x[d * 3 + 2];
    z[3] = x[s * 3 + 0]; z[4] = x[s * 3 + 1]; z[5] = x[s * 3 + 2];
#pragma unroll
    for (int k = 0; k < 32; k++) z[6 + k] = ea[(size_t)e * 32 + k];

    float f0 = sbf[0], f1 = sbf[1], f2 = sbf[2];
    float g0 = sbs[0], g1 = sbs[1], g2 = sbs[2];
#pragma unroll
    for (int k = 0; k < 38; k++) {
        float zk = z[k];
        f0 += zk * sWf[k * 3 + 0];
        f1 += zk * sWf[k * 3 + 1];
        f2 += zk * sWf[k * 3 + 2];
        g0 += zk * sWs[k * 3 + 0];
        g1 += zk * sWs[k * 3 + 1];
        g2 += zk * sWs[k * 3 + 2];
    }
    atomicAdd(&out[d * 3 + 0], sigmoidf_(f0) * softplusf_(g0));
    atomicAdd(&out[d * 3 + 1], sigmoidf_(f1) * softplusf_(g1));
    atomicAdd(&out[d * 3 + 2], sigmoidf_(f2) * softplusf_(g2));
}

// ---------------- projection: relu(h1[N,3] @ Wp[3,128] + bp) ----------------
__global__ void proj_kernel(const float* __restrict__ h3,
                            const float* __restrict__ Wp,
                            const float* __restrict__ bp,
                            float* __restrict__ out) {
    int i = blockIdx.x * blockDim.x + threadIdx.x;
    if (i >= N_NODES * HID) return;
    int n = i >> 7, c = i & 127;
    float a = bp[c] + h3[n * 3 + 0] * Wp[0 * 128 + c]
                    + h3[n * 3 + 1] * Wp[1 * 128 + c]
                    + h3[n * 3 + 2] * Wp[2 * 128 + c];
    out[i] = fmaxf(a, 0.0f);
}

// ---------------- pack combined weight matrix for node pre-projection ----------------
// Wcat columns: [0,128)=Wf rows 0..127 (dst), [128,256)=Ws dst, [256,384)=Wf rows 128..255 (src), [384,512)=Ws src
__global__ void pack_kernel(const float* __restrict__ Wf, const float* __restrict__ bf,
                            const float* __restrict__ Ws, const float* __restrict__ bs) {
    int i = blockIdx.x * blockDim.x + threadIdx.x;  // 128*512 threads
    int k = i >> 9, j = i & 511;
    float w;
    if (j < 128)       w = Wf[k * 128 + j];
    else if (j < 256)  w = Ws[k * 128 + (j - 128)];
    else if (j < 384)  w = Wf[(128 + k) * 128 + (j - 256)];
    else               w = Ws[(128 + k) * 128 + (j - 384)];
    g_Wcat[i] = w;
    if (k == 0) g_bcat[j] = (j < 128) ? bf[j] : ((j < 256) ? bs[j - 128] : 0.0f);
}

// ---------------- node pre-projection GEMM: tab[N,512] = h[N,128] @ Wcat + bcat ----------------
__global__ void __launch_bounds__(256) gemm_kernel(const float* __restrict__ A,
                                                   float* __restrict__ C) {
    __shared__ float sA[16][68];  // [k][m], padded rows (272B, 16B aligned)
    __shared__ float sB[16][64];  // [k][n]
    int bm = blockIdx.y * 64, bn = blockIdx.x * 64;
    int tid = threadIdx.x;
    int tx = tid & 15, ty = tid >> 4;

    float acc[4][4];
#pragma unroll
    for (int i = 0; i < 4; i++)
#pragma unroll
        for (int j = 0; j < 4; j++) acc[i][j] = 0.0f;

    for (int kt = 0; kt < 128; kt += 16) {
#pragma unroll
        for (int p = 0; p < 4; p++) {
            int i = tid + p * 256;          // i in [0,1024)
            int k = i & 15, m = i >> 4;
            int row = bm + m;
            sA[k][m] = (row < N_NODES) ? A[row * 128 + kt + k] : 0.0f;
        }
#pragma unroll
        for (int p = 0; p < 4; p++) {
            int i = tid + p * 256;
            int n = i & 63, k = i >> 6;
            sB[k][n] = g_Wcat[(kt + k) * 512 + bn + n];
        }
        __syncthreads();
#pragma unroll
        for (int k = 0; k < 16; k++) {
            float4 a4 = *reinterpret_cast<const float4*>(&sA[k][ty * 4]);
            float4 b4 = *reinterpret_cast<const float4*>(&sB[k][tx * 4]);
            float a[4] = {a4.x, a4.y, a4.z, a4.w};
            float b[4] = {b4.x, b4.y, b4.z, b4.w};
#pragma unroll
            for (int i = 0; i < 4; i++)
#pragma unroll
                for (int j = 0; j < 4; j++) acc[i][j] += a[i] * b[j];
        }
        __syncthreads();
    }
#pragma unroll
    for (int i = 0; i < 4; i++) {
        int row = bm + ty * 4 + i;
        if (row < N_NODES) {
#pragma unroll
            for (int j = 0; j < 4; j++) {
                int col = bn + tx * 4 + j;
                C[(size_t)row * 512 + col] = acc[i][j] + g_bcat[col];
            }
        }
    }
}

// ---------------- fused edge kernel (conv2/conv3), warp per edge, 4 edges batched ----------------
__global__ void __launch_bounds__(256) edge_kernel(const float* __restrict__ tab,
                                                   const int* __restrict__ src,
                                                   const int* __restrict__ dst,
                                                   const float* __restrict__ ea,
                                                   const float* __restrict__ Wfe,  // rows 256..287 of Wf
                                                   const float* __restrict__ Wse,
                                                   float* __restrict__ out) {
    __shared__ float4 sWf[32 * 32];   // [k][lane] -> float k*128 + lane*4 + j
    __shared__ float4 sWs[32 * 32];
    {
        float* pf = reinterpret_cast<float*>(sWf);
        float* ps = reinterpret_cast<float*>(sWs);
        for (int i = threadIdx.x; i < 32 * 128; i += blockDim.x) {
            pf[i] = Wfe[i];
            ps[i] = Wse[i];
        }
    }
    __syncthreads();

    const int lane = threadIdx.x & 31;
    const int warp = blockIdx.x * (blockDim.x >> 5) + (threadIdx.x >> 5);
    const int nwarps = gridDim.x * (blockDim.x >> 5);
    const int T = 4;

    for (int base = warp * T; base < N_EDGES; base += nwarps * T) {
        float4 accf[T], accs[T];
        float eav[T];
        int dd[T];
#pragma unroll
        for (int t = 0; t < T; t++) {
            int e = base + t;
            if (e < N_EDGES) {
                int d = dst[e], s = src[e];
                dd[t] = d;
                eav[t] = ea[(size_t)e * 32 + lane];
                const float4* td = reinterpret_cast<const float4*>(tab + (size_t)d * 512);
                const float4* ts = reinterpret_cast<const float4*>(tab + (size_t)s * 512);
                float4 a = td[lane];        // f dst part (+bias)
                float4 b = ts[64 + lane];   // f src part
                float4 c = td[32 + lane];   // s dst part (+bias)
                float4 q = ts[96 + lane];   // s src part
                accf[t] = make_float4(a.x + b.x, a.y + b.y, a.z + b.z, a.w + b.w);
                accs[t] = make_float4(c.x + q.x, c.y + q.y, c.z + q.z, c.w + q.w);
            } else {
                dd[t] = -1;
                eav[t] = 0.0f;
                accf[t] = make_float4(0, 0, 0, 0);
                accs[t] = make_float4(0, 0, 0, 0);
            }
        }
#pragma unroll
        for (int k = 0; k < 32; k++) {
            float4 wf = sWf[k * 32 + lane];
            float4 ws = sWs[k * 32 + lane];
#pragma unroll
            for (int t = 0; t < T; t++) {
                float ek = __shfl_sync(0xffffffffu, eav[t], k);
                accf[t].x += ek * wf.x; accf[t].y += ek * wf.y;
                accf[t].z += ek * wf.z; accf[t].w += ek * wf.w;
                accs[t].x += ek * ws.x; accs[t].y += ek * ws.y;
                accs[t].z += ek * ws.z; accs[t].w += ek * ws.w;
            }
        }
#pragma unroll
        for (int t = 0; t < T; t++) {
            if (dd[t] >= 0) {
                float m0 = sigmoidf_(accf[t].x) * softplusf_(accs[t].x);
                float m1 = sigmoidf_(accf[t].y) * softplusf_(accs[t].y);
                float m2 = sigmoidf_(accf[t].z) * softplusf_(accs[t].z);
                float m3 = sigmoidf_(accf[t].w) * softplusf_(accs[t].w);
                float* o = out + (size_t)dd[t] * HID + lane * 4;
                atomicAdd(o + 0, m0);
                atomicAdd(o + 1, m1);
                atomicAdd(o + 2, m2);
                atomicAdd(o + 3, m3);
            }
        }
    }
}

// ---------------- elementwise relu copy ----------------
__global__ void relucopy_kernel(const float* __restrict__ in, float* __restrict__ out) {
    int i = blockIdx.x * blockDim.x + threadIdx.x;
    if (i < N_NODES * HID) out[i] = fmaxf(in[i], 0.0f);
}

// ---------------- pooling: sorted-batch run-length sum into g_pool, counts into g_cnt ----------------
__global__ void pool_kernel(const float* __restrict__ h, const int* __restrict__ batch) {
    int c = threadIdx.x;  // 128 threads = channels
    int n0 = blockIdx.x * 256;
    int n1 = min(n0 + 256, N_NODES);
    if (n0 >= N_NODES) return;
    int cur = batch[n0];
    float run = 0.0f, crun = 0.0f;
    for (int n = n0; n < n1; n++) {
        int b = batch[n];
        if (b != cur) {
            atomicAdd(&g_pool[cur * HID + c], run);
            run = 0.0f;
            if (c == 0) { atomicAdd(&g_cnt[cur], crun); }
            crun = 0.0f;
            cur = b;
        }
        run += fmaxf(h[(size_t)n * HID + c], 0.0f);
        crun += 1.0f;
    }
    atomicAdd(&g_pool[cur * HID + c], run);
    if (c == 0) atomicAdd(&g_cnt[cur], crun);
}

// ---------------- head: relu(pooled @ W1 + b1) @ W2 + b2 ----------------
__global__ void head_kernel(const float* __restrict__ W1, const float* __restrict__ b1,
                            const float* __restrict__ W2, const float* __restrict__ b2,
                            float* __restrict__ out) {
    __shared__ float p[128];
    __shared__ float hid[128];
    int g = blockIdx.x, c = threadIdx.x;
    float invc = 1.0f / fmaxf(g_cnt[g], 1.0f);
    p[c] = g_pool[g * HID + c] * invc;
    __syncthreads();
    float a = b1[c];
#pragma unroll 8
    for (int k = 0; k < 128; k++) a += p[k] * W1[k * 128 + c];
    hid[c] = fmaxf(a, 0.0f);
    __syncthreads();
    if (c < 3) {
        float o = b2[c];
#pragma unroll 8
        for (int k = 0; k < 128; k++) o += hid[k] * W2[k * 3 + c];
        out[g * 3 + c] = o;
    }
}

// ---------------- launch ----------------
extern "C" void kernel_launch(void* const* d_in, const int* in_sizes, int n_in,
                              void* d_out, int out_size) {
    const float* x   = (const float*)d_in[0];
    const int*   ei  = (const int*)d_in[1];
    const float* ea  = (const float*)d_in[2];
    const int*   bat = (const int*)d_in[3];
    const float* Wf1 = (const float*)d_in[4];
    const float* bf1 = (const float*)d_in[5];
    const float* Ws1 = (const float*)d_in[6];
    const float* bs1 = (const float*)d_in[7];
    const float* Wp  = (const float*)d_in[8];
    const float* bp  = (const float*)d_in[9];
    const float* Wf2 = (const float*)d_in[10];
    const float* bf2 = (const float*)d_in[11];
    const float* Ws2 = (const float*)d_in[12];
    const float* bs2 = (const float*)d_in[13];
    const float* Wf3 = (const float*)d_in[14];
    const float* bf3 = (const float*)d_in[15];
    const float* Ws3 = (const float*)d_in[16];
    const float* bs3 = (const float*)d_in[17];
    const float* W1  = (const float*)d_in[18];
    const float* b1  = (const float*)d_in[19];
    const float* W2  = (const float*)d_in[20];
    const float* b2  = (const float*)d_in[21];
    float* out = (float*)d_out;

    const int* src = ei;
    const int* dst = ei + N_EDGES;

    void *p_feat0, *p_featA, *p_featB, *p_tab, *p_pool, *p_cnt;
    cudaGetSymbolAddress(&p_feat0, g_feat0);
    cudaGetSymbolAddress(&p_featA, g_featA);
    cudaGetSymbolAddress(&p_featB, g_featB);
    cudaGetSymbolAddress(&p_tab,   g_tab);
    cudaGetSymbolAddress(&p_pool,  g_pool);
    cudaGetSymbolAddress(&p_cnt,   g_cnt);

    // conv1: h1 = x + agg
    cudaMemcpyAsync(p_feat0, x, (size_t)N_NODES * 3 * sizeof(float),
                    cudaMemcpyDeviceToDevice, 0);
    conv1_kernel<<<(N_EDGES + 255) / 256, 256>>>(x, src, dst, ea, Wf1, bf1, Ws1, bs1,
                                                 (float*)p_feat0);
    // hA = relu(h1 @ Wp + bp)
    proj_kernel<<<(N_NODES * HID + 255) / 256, 256>>>((float*)p_feat0, Wp, bp,
                                                      (float*)p_featA);

    // ---- conv2: hB_pre = hA + agg2 ----
    pack_kernel<<<(128 * 512) / 256, 256>>>(Wf2, bf2, Ws2, bs2);
    gemm_kernel<<<dim3(8, (N_NODES + 63) / 64), 256>>>((float*)p_featA, (float*)p_tab);
    cudaMemcpyAsync(p_featB, p_featA, (size_t)N_NODES * HID * sizeof(float),
                    cudaMemcpyDeviceToDevice, 0);
    edge_kernel<<<2048, 256>>>((float*)p_tab, src, dst, ea,
                               Wf2 + 256 * 128, Ws2 + 256 * 128, (float*)p_featB);

    // ---- conv3: hA = relu(hB_pre); hB_pre3 = hA + agg3 ----
    relucopy_kernel<<<(N_NODES * HID + 255) / 256, 256>>>((float*)p_featB, (float*)p_featA);
    pack_kernel<<<(128 * 512) / 256, 256>>>(Wf3, bf3, Ws3, bs3);
    gemm_kernel<<<dim3(8, (N_NODES + 63) / 64), 256>>>((float*)p_featA, (float*)p_tab);
    cudaMemcpyAsync(p_featB, p_featA, (size_t)N_NODES * HID * sizeof(float),
                    cudaMemcpyDeviceToDevice, 0);
    edge_kernel<<<2048, 256>>>((float*)p_tab, src, dst, ea,
                               Wf3 + 256 * 128, Ws3 + 256 * 128, (float*)p_featB);

    // ---- pool (applies final relu) + head ----
    cudaMemsetAsync(p_pool, 0, 64 * HID * sizeof(float), 0);
    cudaMemsetAsync(p_cnt, 0, 64 * sizeof(float), 0);
    pool_kernel<<<(N_NODES + 255) / 256, 128>>>((float*)p_featB, bat);
    head_kernel<<<64, 128>>>(W1, b1, W2, b2, out);
}

// round 9
// speedup vs baseline: 1.0753x; 1.0753x over previous
#include <cuda_runtime.h>
#include <math.h>
#include <stdint.h>

#define N_NODES 100000
#define N_EDGES 1600000
#define HID 128

// ---------------- scratch (static __device__, no allocation) ----------------
__device__ float g_feat0[N_NODES * 3];
__device__ float g_featA[N_NODES * HID];
__device__ float g_featB[N_NODES * HID];
__device__ float g_tab[(size_t)N_NODES * 512];   // per-node pre-projection table
__device__ float g_et[(size_t)N_EDGES * 256];    // per-edge term (sorted order)
__device__ float g_Wcat[128 * 512];              // [Wf_dst|Ws_dst|Wf_src|Ws_src]
__device__ float g_bcat[512];
__device__ float g_We[32 * 256];                 // [Wfe|Wse]
__device__ float g_pool[64 * HID];
__device__ float g_cnt[64];
// CSR
__device__ int g_cntN[N_NODES];
__device__ int g_ptr[N_NODES + 1];
__device__ int g_perm[N_EDGES];
__device__ int g_srcs[N_EDGES];

// ---------------- math helpers ----------------
__device__ __forceinline__ float gatef(float f, float s) {
    float sig = __fdividef(1.0f, 1.0f + __expf(-f));
    float sp = (s > 20.0f) ? s : __logf(1.0f + __expf(s));
    return sig * sp;
}

__device__ __forceinline__ float tf32r(float x) {
    uint32_t u;
    asm("cvt.rna.tf32.f32 %0, %1;" : "=r"(u) : "f"(x));
    return __uint_as_float(u);
}

__device__ __forceinline__ void mma_tf32(float* c, uint32_t a0, uint32_t a1,
                                         uint32_t a2, uint32_t a3,
                                         uint32_t b0, uint32_t b1) {
    asm volatile(
        "mma.sync.aligned.m16n8k8.row.col.f32.tf32.tf32.f32 "
        "{%0,%1,%2,%3},{%4,%5,%6,%7},{%8,%9},{%0,%1,%2,%3};"
        : "+f"(c[0]), "+f"(c[1]), "+f"(c[2]), "+f"(c[3])
        : "r"(a0), "r"(a1), "r"(a2), "r"(a3), "r"(b0), "r"(b1));
}

// ---------------- CSR construction ----------------
__global__ void __launch_bounds__(256) hist_kernel(const int* __restrict__ dst) {
    int e = blockIdx.x * blockDim.x + threadIdx.x;
    if (e < N_EDGES) atomicAdd(&g_cntN[dst[e]], 1);
}

__global__ void __launch_bounds__(1024) scan_kernel() {  // single block
    __shared__ int ssum[1024];
    const int CH = 98;  // 1024*98 >= 100000
    int t = threadIdx.x;
    int base = t * CH;
    int s = 0;
#pragma unroll 1
    for (int i = 0; i < CH; i++) {
        int idx = base + i;
        if (idx < N_NODES) s += g_cntN[idx];
    }
    ssum[t] = s;
    __syncthreads();
    for (int off = 1; off < 1024; off <<= 1) {
        int v = (t >= off) ? ssum[t - off] : 0;
        __syncthreads();
        ssum[t] += v;
        __syncthreads();
    }
    int run = ssum[t] - s;  // exclusive
#pragma unroll 1
    for (int i = 0; i < CH; i++) {
        int idx = base + i;
        if (idx < N_NODES) {
            g_ptr[idx] = run;
            run += g_cntN[idx];
        }
    }
    if (t == 1023) g_ptr[N_NODES] = N_EDGES;
}

__global__ void __launch_bounds__(256) scatter_kernel(const int* __restrict__ src,
                                                      const int* __restrict__ dst) {
    int e = blockIdx.x * blockDim.x + threadIdx.x;
    if (e >= N_EDGES) return;
    int d = dst[e];
    int pos = atomicAdd(&g_cntN[d], 1);
    int slot = g_ptr[d] + pos;
    g_perm[slot] = e;
    g_srcs[slot] = src[e];
}

// ---------------- conv1: CGConv at C=3 (thread per edge, atomics) ----------------
__global__ void __launch_bounds__(256) conv1_kernel(
        const float* __restrict__ x,
        const int* __restrict__ src,
        const int* __restrict__ dst,
        const float* __restrict__ ea,
        const float* __restrict__ Wf,
        const float* __restrict__ bf,
        const float* __restrict__ Ws,
        const float* __restrict__ bs,
        float* __restrict__ out) {
    __shared__ float sWf[38 * 3];
    __shared__ float sWs[38 * 3];
    __shared__ float sbf[3], sbs[3];
    for (int i = threadIdx.x; i < 38 * 3; i += blockDim.x) {
        sWf[i] = Wf[i];
        sWs[i] = Ws[i];
    }
    if (threadIdx.x < 3) { sbf[threadIdx.x] = bf[threadIdx.x]; sbs[threadIdx.x] = bs[threadIdx.x]; }
    __syncthreads();

    int e = blockIdx.x * blockDim.x + threadIdx.x;
    if (e >= N_EDGES) return;
    int s = src[e], d = dst[e];

    float z[38];
    z[0] = x[d * 3 + 0]; z[1] = x[d * 3 + 1]; z[2] = x[d * 3 + 2];
    z[3] = x[s * 3 + 0]; z[4] = x[s * 3 + 1]; z[5] = x[s * 3 + 2];
#pragma unroll
    for (int k = 0; k < 32; k++) z[6 + k] = ea[(size_t)e * 32 + k];

    float f0 = sbf[0], f1 = sbf[1], f2 = sbf[2];
    float g0 = sbs[0], g1 = sbs[1], g2 = sbs[2];
#pragma unroll
    for (int k = 0; k < 38; k++) {
        float zk = z[k];
        f0 += zk * sWf[k * 3 + 0];
        f1 += zk * sWf[k * 3 + 1];
        f2 += zk * sWf[k * 3 + 2];
        g0 += zk * sWs[k * 3 + 0];
        g1 += zk * sWs[k * 3 + 1];
        g2 += zk * sWs[k * 3 + 2];
    }
    atomicAdd(&out[d * 3 + 0], gatef(f0, g0));
    atomicAdd(&out[d * 3 + 1], gatef(f1, g1));
    atomicAdd(&out[d * 3 + 2], gatef(f2, g2));
}

// ---------------- projection ----------------
__global__ void __launch_bounds__(256) proj_kernel(
        const float* __restrict__ h3,
        const float* __restrict__ Wp,
        const float* __restrict__ bp,
        float* __restrict__ out) {
    int i = blockIdx.x * blockDim.x + threadIdx.x;
    if (i >= N_NODES * HID) return;
    int n = i >> 7, c = i & 127;
    float a = bp[c] + h3[n * 3 + 0] * Wp[0 * 128 + c]
                    + h3[n * 3 + 1] * Wp[1 * 128 + c]
                    + h3[n * 3 + 2] * Wp[2 * 128 + c];
    out[i] = fmaxf(a, 0.0f);
}

// ---------------- weight packing ----------------
__global__ void __launch_bounds__(256) pack_kernel(
        const float* __restrict__ Wf, const float* __restrict__ bf,
        const float* __restrict__ Ws, const float* __restrict__ bs) {
    int i = blockIdx.x * blockDim.x + threadIdx.x;  // 128*512
    int k = i >> 9, j = i & 511;
    float w;
    if (j < 128)       w = Wf[k * 128 + j];
    else if (j < 256)  w = Ws[k * 128 + (j - 128)];
    else if (j < 384)  w = Wf[(128 + k) * 128 + (j - 256)];
    else               w = Ws[(128 + k) * 128 + (j - 384)];
    g_Wcat[i] = w;
    if (k == 0) g_bcat[j] = (j < 128) ? bf[j] : ((j < 256) ? bs[j - 128] : 0.0f);
}

__global__ void __launch_bounds__(256) packWe_kernel(
        const float* __restrict__ Wf, const float* __restrict__ Ws) {
    int i = blockIdx.x * blockDim.x + threadIdx.x;  // 32*256
    int k = i >> 8, c = i & 255;
    g_We[i] = (c < 128) ? Wf[(256 + k) * 128 + c] : Ws[(256 + k) * 128 + (c - 128)];
}

// ---------------- generic tf32 mma GEMM: C[M,N] = A[M,K] @ B[K,N] (+bias) ----------
// Block: 256 threads (8 warps), tile 128 rows. Loops over NCHUNKS*64 cols.
template <int KCHUNKS, int NCHUNKS, bool GATHER, bool BIAS>
__global__ void __launch_bounds__(256) mma_gemm_kernel(
    const float* __restrict__ A, const float* __restrict__ B,
    const float* __restrict__ bias, const int* __restrict__ perm,
    float* __restrict__ C, int M) {
    __shared__ float sraw[8704];             // 34.8 KB
    float* sA = sraw;                        // [128][36]
    float* sB = sraw + 128 * 36;             // [32][68]
    float* sC = sraw;                        // [128][68] (overlaps A+B)
    const int K = KCHUNKS * 32, N = NCHUNKS * 64;
    int t = threadIdx.x, lane = t & 31, w = t >> 5;
    int rowbase = blockIdx.x * 128;

#pragma unroll 1
    for (int nch = 0; nch < NCHUNKS; nch++) {
        float acc[8][4];
#pragma unroll
        for (int nt = 0; nt < 8; nt++)
#pragma unroll
            for (int q = 0; q < 4; q++) acc[nt][q] = 0.0f;

#pragma unroll 1
        for (int kch = 0; kch < KCHUNKS; kch++) {
            // stage A 128x32
#pragma unroll
            for (int p = 0; p < 16; p++) {
                int i = t + p * 256;
                int r = i >> 5, k = i & 31;
                int row = rowbase + r;
                float v = 0.0f;
                if (row < M) {
                    int ar = GATHER ? perm[row] : row;
                    v = A[(size_t)ar * K + kch * 32 + k];
                }
                sA[r * 36 + k] = tf32r(v);
            }
            // stage B 32x64
#pragma unroll
            for (int p = 0; p < 8; p++) {
                int i = t + p * 256;
                int kk = i >> 6, n = i & 63;
                sB[kk * 68 + n] = tf32r(B[(size_t)(kch * 32 + kk) * N + nch * 64 + n]);
            }
            __syncthreads();
            // compute
#pragma unroll
            for (int ks = 0; ks < 4; ks++) {
                int r0 = w * 16 + (lane >> 2);
                int k0 = ks * 8 + (lane & 3);
                uint32_t a0 = __float_as_uint(sA[r0 * 36 + k0]);
                uint32_t a1 = __float_as_uint(sA[(r0 + 8) * 36 + k0]);
                uint32_t a2 = __float_as_uint(sA[r0 * 36 + k0 + 4]);
                uint32_t a3 = __float_as_uint(sA[(r0 + 8) * 36 + k0 + 4]);
#pragma unroll
                for (int nt = 0; nt < 8; nt++) {
                    int bk = ks * 8 + (lane & 3);
                    int bn = nt * 8 + (lane >> 2);
                    uint32_t b0 = __float_as_uint(sB[bk * 68 + bn]);
                    uint32_t b1 = __float_as_uint(sB[(bk + 4) * 68 + bn]);
                    mma_tf32(acc[nt], a0, a1, a2, a3, b0, b1);
                }
            }
            __syncthreads();
        }
        // epilogue: fragments -> sC
#pragma unroll
        for (int nt = 0; nt < 8; nt++) {
            int r = w * 16 + (lane >> 2);
            int cc = nt * 8 + 2 * (lane & 3);
            sC[r * 68 + cc] = acc[nt][0];
            sC[r * 68 + cc + 1] = acc[nt][1];
            sC[(r + 8) * 68 + cc] = acc[nt][2];
            sC[(r + 8) * 68 + cc + 1] = acc[nt][3];
        }
        __syncthreads();
        // coalesced store
#pragma unroll
        for (int p = 0; p < 32; p++) {
            int i = t + p * 256;
            int r = i >> 6, n = i & 63;
            int row = rowbase + r;
            if (row < M) {
                float v = sC[r * 68 + n];
                if (BIAS) v += bias[nch * 64 + n];
                C[(size_t)row * N + nch * 64 + n] = v;
            }
        }
        __syncthreads();
    }
}

// ---------------- aggregation: warp per dst node, CSR, no atomics ----------------
__global__ void __launch_bounds__(256) agg_kernel(
    const float* __restrict__ tab, const int* __restrict__ ptr,
    const int* __restrict__ srcs, const float* __restrict__ et,
    const float* __restrict__ base, float* __restrict__ out) {
    int wgl = (blockIdx.x * blockDim.x + threadIdx.x) >> 5;
    int lane = threadIdx.x & 31;
    if (wgl >= N_NODES) return;
    int d = wgl;
    int i0 = ptr[d], i1 = ptr[d + 1];
    const float4* tabv = reinterpret_cast<const float4*>(tab);
    float4 fd = tabv[(size_t)d * 128 + lane];
    float4 sd = tabv[(size_t)d * 128 + 32 + lane];
    float ax = 0.0f, ay = 0.0f, az = 0.0f, aw = 0.0f;
#pragma unroll 2
    for (int i = i0; i < i1; i++) {
        int s = srcs[i];
        const float4* ev = reinterpret_cast<const float4*>(et + (size_t)i * 256);
        float4 fe = __ldcs(ev + lane);
        float4 se = __ldcs(ev + 32 + lane);
        const float4* sv = reinterpret_cast<const float4*>(tab + (size_t)s * 512);
        float4 fs = __ldg(sv + 64 + lane);
        float4 ss = __ldg(sv + 96 + lane);
        ax += gatef(fd.x + fe.x + fs.x, sd.x + se.x + ss.x);
        ay += gatef(fd.y + fe.y + fs.y, sd.y + se.y + ss.y);
        az += gatef(fd.z + fe.z + fs.z, sd.z + se.z + ss.z);
        aw += gatef(fd.w + fe.w + fs.w, sd.w + se.w + ss.w);
    }
    float4 b = reinterpret_cast<const float4*>(base)[(size_t)d * 32 + lane];
    float4 o;
    o.x = fmaxf(b.x + ax, 0.0f);
    o.y = fmaxf(b.y + ay, 0.0f);
    o.z = fmaxf(b.z + az, 0.0f);
    o.w = fmaxf(b.w + aw, 0.0f);
    reinterpret_cast<float4*>(out)[(size_t)d * 32 + lane] = o;
}

// ---------------- pooling ----------------
__global__ void __launch_bounds__(128) pool_kernel(
        const float* __restrict__ h, const int* __restrict__ batch) {
    int c = threadIdx.x;
    int n0 = blockIdx.x * 256;
    int n1 = min(n0 + 256, N_NODES);
    if (n0 >= N_NODES) return;
    int cur = batch[n0];
    float run = 0.0f, crun = 0.0f;
    for (int n = n0; n < n1; n++) {
        int b = batch[n];
        if (b != cur) {
            atomicAdd(&g_pool[cur * HID + c], run);
            run = 0.0f;
            if (c == 0) atomicAdd(&g_cnt[cur], crun);
            crun = 0.0f;
            cur = b;
        }
        run += fmaxf(h[(size_t)n * HID + c], 0.0f);
        crun += 1.0f;
    }
    atomicAdd(&g_pool[cur * HID + c], run);
    if (c == 0) atomicAdd(&g_cnt[cur], crun);
}

// ---------------- head ----------------
__global__ void __launch_bounds__(128) head_kernel(
        const float* __restrict__ W1, const float* __restrict__ b1,
        const float* __restrict__ W2, const float* __restrict__ b2,
        float* __restrict__ out) {
    __shared__ float p[128];
    __shared__ float hid[128];
    int g = blockIdx.x, c = threadIdx.x;
    float invc = 1.0f / fmaxf(g_cnt[g], 1.0f);
    p[c] = g_pool[g * HID + c] * invc;
    __syncthreads();
    float a = b1[c];
#pragma unroll 8
    for (int k = 0; k < 128; k++) a += p[k] * W1[k * 128 + c];
    hid[c] = fmaxf(a, 0.0f);
    __syncthreads();
    if (c < 3) {
        float o = b2[c];
#pragma unroll 8
        for (int k = 0; k < 128; k++) o += hid[k] * W2[k * 3 + c];
        out[g * 3 + c] = o;
    }
}

// ---------------- launch ----------------
extern "C" void kernel_launch(void* const* d_in, const int* in_sizes, int n_in,
                              void* d_out, int out_size) {
    const float* x   = (const float*)d_in[0];
    const int*   ei  = (const int*)d_in[1];
    const float* ea  = (const float*)d_in[2];
    const int*   bat = (const int*)d_in[3];
    const float* Wf1 = (const float*)d_in[4];
    const float* bf1 = (const float*)d_in[5];
    const float* Ws1 = (const float*)d_in[6];
    const float* bs1 = (const float*)d_in[7];
    const float* Wp  = (const float*)d_in[8];
    const float* bp  = (const float*)d_in[9];
    const float* Wf2 = (const float*)d_in[10];
    const float* bf2 = (const float*)d_in[11];
    const float* Ws2 = (const float*)d_in[12];
    const float* bs2 = (const float*)d_in[13];
    const float* Wf3 = (const float*)d_in[14];
    const float* bf3 = (const float*)d_in[15];
    const float* Ws3 = (const float*)d_in[16];
    const float* bs3 = (const float*)d_in[17];
    const float* W1  = (const float*)d_in[18];
    const float* b1  = (const float*)d_in[19];
    const float* W2  = (const float*)d_in[20];
    const float* b2  = (const float*)d_in[21];
    float* out = (float*)d_out;

    const int* src = ei;
    const int* dst = ei + N_EDGES;

    void *p_feat0, *p_featA, *p_featB, *p_tab, *p_et, *p_Wcat, *p_bcat, *p_We;
    void *p_pool, *p_cnt, *p_cntN, *p_ptr, *p_perm, *p_srcs;
    cudaGetSymbolAddress(&p_feat0, g_feat0);
    cudaGetSymbolAddress(&p_featA, g_featA);
    cudaGetSymbolAddress(&p_featB, g_featB);
    cudaGetSymbolAddress(&p_tab,   g_tab);
    cudaGetSymbolAddress(&p_et,    g_et);
    cudaGetSymbolAddress(&p_Wcat,  g_Wcat);
    cudaGetSymbolAddress(&p_bcat,  g_bcat);
    cudaGetSymbolAddress(&p_We,    g_We);
    cudaGetSymbolAddress(&p_pool,  g_pool);
    cudaGetSymbolAddress(&p_cnt,   g_cnt);
    cudaGetSymbolAddress(&p_cntN,  g_cntN);
    cudaGetSymbolAddress(&p_ptr,   g_ptr);
    cudaGetSymbolAddress(&p_perm,  g_perm);
    cudaGetSymbolAddress(&p_srcs,  g_srcs);

    const int EB = (N_EDGES + 255) / 256;

    // ---- CSR construction ----
    cudaMemsetAsync(p_cntN, 0, N_NODES * sizeof(int), 0);
    hist_kernel<<<EB, 256>>>(dst);
    scan_kernel<<<1, 1024>>>();
    cudaMemsetAsync(p_cntN, 0, N_NODES * sizeof(int), 0);
    scatter_kernel<<<EB, 256>>>(src, dst);

    // ---- conv1 + projection ----
    cudaMemcpyAsync(p_feat0, x, (size_t)N_NODES * 3 * sizeof(float),
                    cudaMemcpyDeviceToDevice, 0);
    conv1_kernel<<<EB, 256>>>(x, src, dst, ea, Wf1, bf1, Ws1, bs1, (float*)p_feat0);
    proj_kernel<<<(N_NODES * HID + 255) / 256, 256>>>((float*)p_feat0, Wp, bp,
                                                      (float*)p_featA);

    const int NGB = (N_NODES + 127) / 128;   // 782
    const int EGB = N_EDGES / 128;           // 12500
    const int AGB = (N_NODES * 32 + 255) / 256;  // 12500

    // ---- conv2 ----
    pack_kernel<<<(128 * 512) / 256, 256>>>(Wf2, bf2, Ws2, bs2);
    packWe_kernel<<<(32 * 256) / 256, 256>>>(Wf2, Ws2);
    mma_gemm_kernel<4, 8, false, true><<<NGB, 256>>>(
        (const float*)p_featA, (const float*)p_Wcat, (const float*)p_bcat,
        nullptr, (float*)p_tab, N_NODES);
    mma_gemm_kernel<1, 4, true, false><<<EGB, 256>>>(
        ea, (const float*)p_We, nullptr, (const int*)p_perm,
        (float*)p_et, N_EDGES);
    agg_kernel<<<AGB, 256>>>((const float*)p_tab, (const int*)p_ptr,
                             (const int*)p_srcs, (const float*)p_et,
                             (const float*)p_featA, (float*)p_featB);

    // ---- conv3 ----
    pack_kernel<<<(128 * 512) / 256, 256>>>(Wf3, bf3, Ws3, bs3);
    packWe_kernel<<<(32 * 256) / 256, 256>>>(Wf3, Ws3);
    mma_gemm_kernel<4, 8, false, true><<<NGB, 256>>>(
        (const float*)p_featB, (const float*)p_Wcat, (const float*)p_bcat,
        nullptr, (float*)p_tab, N_NODES);
    mma_gemm_kernel<1, 4, true, false><<<EGB, 256>>>(
        ea, (const float*)p_We, nullptr, (const int*)p_perm,
        (float*)p_et, N_EDGES);
    agg_kernel<<<AGB, 256>>>((const float*)p_tab, (const int*)p_ptr,
                             (const int*)p_srcs, (const float*)p_et,
                             (const float*)p_featB, (float*)p_featA);

    // ---- pool + head ----
    cudaMemsetAsync(p_pool, 0, 64 * HID * sizeof(float), 0);
    cudaMemsetAsync(p_cnt, 0, 64 * sizeof(float), 0);
    pool_kernel<<<(N_NODES + 255) / 256, 128>>>((float*)p_featA, bat);
    head_kernel<<<64, 128>>>(W1, b1, W2, b2, out);
}